// round 14
// baseline (speedup 1.0000x reference)
#include <cuda_runtime.h>
#include <cuda_bf16.h>
#include <cstdint>
#include <math.h>

#define BB 8192
typedef unsigned long long u64;
typedef unsigned int u32;

// ---------------- device scratch (allocation-free) ----------------
__device__ __align__(16) __nv_bfloat16 g_pooled0[BB * 3328];
__device__ __align__(16) __nv_bfloat16 g_pooled1[BB * 1536];
__device__ __align__(16) __nv_bfloat16 g_h[BB * 1584];   // [ip(528) | aug(1056)] per row
__device__ __align__(16) __nv_bfloat16 g_Wt0[96 * 3328]; // fc0 W transposed [N][K] bf16
__device__ __align__(16) __nv_bfloat16 g_Wt1[96 * 1536];
__device__ __align__(16) __nv_bfloat16 g_Wt2[128 * 1584];
__device__ u32 g_ij[528];                                // (i*38)<<16 | (j*38) row offsets

// ---------------- helpers ----------------
__device__ __forceinline__ float tanh_fast(float x) {
    float y;
    asm("tanh.approx.f32 %0, %1;" : "=f"(y) : "f"(x));
    return y;
}
__device__ __forceinline__ void cp16(void* dst, const void* src, bool p) {
    u32 d = (u32)__cvta_generic_to_shared(dst);
    int sz = p ? 16 : 0;
    asm volatile("cp.async.cg.shared.global [%0], [%1], 16, %2;\n"
                 :: "r"(d), "l"(src), "r"(sz));
}
__device__ __forceinline__ void cp_commit() { asm volatile("cp.async.commit_group;\n"); }
template <int N> __device__ __forceinline__ void cp_wait() {
    asm volatile("cp.async.wait_group %0;\n" :: "n"(N));
}
__device__ __forceinline__ void mma_bf16(float* c, const u32* a, const u32* b) {
    asm volatile(
        "mma.sync.aligned.m16n8k16.row.col.f32.bf16.bf16.f32 "
        "{%0,%1,%2,%3}, {%4,%5,%6,%7}, {%8,%9}, {%0,%1,%2,%3};\n"
        : "+f"(c[0]), "+f"(c[1]), "+f"(c[2]), "+f"(c[3])
        : "r"(a[0]), "r"(a[1]), "r"(a[2]), "r"(a[3]), "r"(b[0]), "r"(b[1]));
}
// packed f32x2 ops (sm_103a). fma2(a,b,c) = a*b + c
__device__ __forceinline__ u64 pk2(float lo, float hi) {
    u64 r; asm("mov.b64 %0, {%1, %2};" : "=l"(r) : "f"(lo), "f"(hi)); return r;
}
__device__ __forceinline__ void upk2(u64 v, float& lo, float& hi) {
    asm("mov.b64 {%0, %1}, %2;" : "=f"(lo), "=f"(hi) : "l"(v));
}
__device__ __forceinline__ u64 fma2(u64 a, u64 b, u64 c) {
    u64 d; asm("fma.rn.f32x2 %0, %1, %2, %3;" : "=l"(d) : "l"(a), "l"(b), "l"(c)); return d;
}
__device__ __forceinline__ u32 packbf(float lo, float hi) {
    __nv_bfloat162 h = __floats2bfloat162_rn(lo, hi);   // .x = lo (low address)
    return *(u32*)&h;
}

// ---------------- W transpose + convert (all three, one launch) ----------------
__device__ __forceinline__ void convW_tile(const float* __restrict__ W,
                                           __nv_bfloat16* __restrict__ Wt,
                                           int K, int N, int bx, int by,
                                           float (*t)[33], int tx, int ty) {
    int k0 = bx * 32, n0 = by * 32;
    #pragma unroll
    for (int r = 0; r < 32; r += 8) {
        int k = k0 + ty + r, n = n0 + tx;
        if (k < K && n < N) t[ty + r][tx] = W[(size_t)k * N + n];
    }
    __syncthreads();
    #pragma unroll
    for (int r = 0; r < 32; r += 8) {
        int n = n0 + ty + r, k = k0 + tx;
        if (k < K && n < N) Wt[(size_t)n * K + k] = __float2bfloat16_rn(t[tx][ty + r]);
    }
}

__global__ void convW_all(const float* __restrict__ W0, const float* __restrict__ W1,
                          const float* __restrict__ W2,
                          __nv_bfloat16* __restrict__ Wt0, __nv_bfloat16* __restrict__ Wt1,
                          __nv_bfloat16* __restrict__ Wt2) {
    __shared__ float t[32][33];
    int tx = threadIdx.x, ty = threadIdx.y;
    int y = blockIdx.y, x = blockIdx.x;
    if (y < 3) {
        convW_tile(W0, Wt0, 3328, 96, x, y, t, tx, ty);           // 104 x 3
    } else if (y < 6) {
        if (x < 48) convW_tile(W1, Wt1, 1536, 96, x, y - 3, t, tx, ty);
    } else {
        if (x < 50) convW_tile(W2, Wt2, 1584, 128, x, y - 6, t, tx, ty);
    }
}

// ---------------- stage A: embed + conv0 + pool + conv1 + pool (fused) ----------------
__global__ __launch_bounds__(256, 4) void stageA_kernel(
    const int* __restrict__ sparse, const float* __restrict__ dense,
    const float* __restrict__ gtab, const float* __restrict__ gW, const float* __restrict__ gb,
    const float* __restrict__ ctab, const float* __restrict__ cW, const float* __restrict__ cb,
    const float* __restrict__ k0, const float* __restrict__ b0,
    const float* __restrict__ k1, const float* __restrict__ b1) {
    __shared__ int sidx[26];
    __shared__ __align__(16) float xs0[27 * 32];     // gen embedding [h][w]
    __shared__ __align__(16) float xs1[8 * 416];     // conv0 pooled, CHW [c][13*32]
    __shared__ __align__(16) float ks0[56];
    __shared__ __align__(16) float ks1[448];
    __shared__ __align__(16) float bs0[8];
    __shared__ __align__(16) float bs1[8];

    int b = blockIdx.x, tid = threadIdx.x;

    // block 0 publishes the gram (i,j) row-offset LUT (gram runs 2 launches later)
    if (b == 0) {
        for (int p = tid; p < 528; p += 256) {
            int i = 0, base = 0;
            while (base + (32 - i) <= p) { base += 32 - i; i++; }
            int j = i + 1 + (p - base);
            g_ij[p] = ((u32)(i * 38) << 16) | (u32)(j * 38);
        }
    }

    if (tid < 26) sidx[tid] = sparse[b * 26 + tid];
    if (tid < 56) ks0[tid] = k0[tid];
    if (tid < 8)  bs0[tid] = b0[tid];
    if (tid >= 8 && tid < 16) bs1[tid - 8] = b1[tid - 8];
    for (int i = tid; i < 448; i += 256) ks1[i] = k1[i];
    __syncthreads();

    __nv_bfloat16* hrow = &g_h[(size_t)b * 1584 + 528];   // aug region (bf16)
    for (int i = tid; i < 832; i += 256) {
        int s = i >> 5, d = i & 31;
        int ix = sidx[s];
        xs0[i]  = gtab[ix * 32 + d];
        hrow[i] = __float2bfloat16_rn(ctab[ix * 32 + d]);
    }
    if (tid < 32) {
        int d = tid;
        float dng = gb[d], dnc = cb[d];
        float xd[13];
        #pragma unroll
        for (int j = 0; j < 13; j++) xd[j] = dense[b * 13 + j];
        #pragma unroll
        for (int j = 0; j < 13; j++) {
            dng += xd[j] * gW[j * 32 + d];
            dnc += xd[j] * cW[j * 32 + d];
        }
        xs0[832 + d]  = dng;
        hrow[832 + d] = __float2bfloat16_rn(dnc);
    }
    __syncthreads();

    // conv0 (7x1, 1->8) + pool2 + tanh, f32x2 packed over f-pairs
    for (int o = tid; o < 416; o += 256) {
        int w = o & 31, i = o >> 5;
        u64 acc0[4], acc1[4];
        #pragma unroll
        for (int fp = 0; fp < 4; fp++) {
            u64 bv = *(const u64*)&bs0[fp * 2];
            acc0[fp] = bv; acc1[fp] = bv;
        }
        #pragma unroll
        for (int k = 0; k < 7; k++) {
            int ha = 2 * i + k - 3, hb = ha + 1;
            float xa = ((unsigned)ha < 27u) ? xs0[ha * 32 + w] : 0.f;
            float xb = ((unsigned)hb < 27u) ? xs0[hb * 32 + w] : 0.f;
            u64 xap = pk2(xa, xa), xbp = pk2(xb, xb);
            #pragma unroll
            for (int fp = 0; fp < 4; fp++) {
                u64 kp = *(const u64*)&ks0[k * 8 + fp * 2];
                acc0[fp] = fma2(xap, kp, acc0[fp]);
                acc1[fp] = fma2(xbp, kp, acc1[fp]);
            }
        }
        float r[8];
        #pragma unroll
        for (int fp = 0; fp < 4; fp++) {
            float a0l, a0h, a1l, a1h;
            upk2(acc0[fp], a0l, a0h);
            upk2(acc1[fp], a1l, a1h);
            r[fp * 2]     = tanh_fast(fmaxf(a0l, a1l));
            r[fp * 2 + 1] = tanh_fast(fmaxf(a0h, a1h));
        }
        uint4 pv;
        pv.x = packbf(r[0], r[1]); pv.y = packbf(r[2], r[3]);
        pv.z = packbf(r[4], r[5]); pv.w = packbf(r[6], r[7]);
        *(uint4*)&g_pooled0[(size_t)b * 3328 + (i * 32 + w) * 8] = pv;
        #pragma unroll
        for (int f = 0; f < 8; f++) xs1[f * 416 + i * 32 + w] = r[f];
    }
    __syncthreads();

    // conv1 (7x1, 8->8) + pool2 + tanh; CHW smem reads, f32x2 packed.
    // k-loop rolled to cap live registers under the 64-reg budget (no spills).
    if (tid < 192) {
        int w = tid & 31, i = tid >> 5;   // i in 0..5
        u64 acc0[4], acc1[4];
        #pragma unroll
        for (int fp = 0; fp < 4; fp++) {
            u64 bv = *(const u64*)&bs1[fp * 2];
            acc0[fp] = bv; acc1[fp] = bv;
        }
        #pragma unroll 1
        for (int k = 0; k < 7; k++) {
            int ha = 2 * i + k - 3, hb = ha + 1;
            bool pa = (unsigned)ha < 13u, pb = (unsigned)hb < 13u;
            #pragma unroll
            for (int c = 0; c < 8; c++) {
                float xa = pa ? xs1[c * 416 + ha * 32 + w] : 0.f;
                float xb = pb ? xs1[c * 416 + hb * 32 + w] : 0.f;
                u64 xap = pk2(xa, xa), xbp = pk2(xb, xb);
                #pragma unroll
                for (int fp = 0; fp < 4; fp++) {
                    u64 kp = *(const u64*)&ks1[(k * 8 + c) * 8 + fp * 2];
                    acc0[fp] = fma2(xap, kp, acc0[fp]);
                    acc1[fp] = fma2(xbp, kp, acc1[fp]);
                }
            }
        }
        float r[8];
        #pragma unroll
        for (int fp = 0; fp < 4; fp++) {
            float a0l, a0h, a1l, a1h;
            upk2(acc0[fp], a0l, a0h);
            upk2(acc1[fp], a1l, a1h);
            r[fp * 2]     = tanh_fast(fmaxf(a0l, a1l));
            r[fp * 2 + 1] = tanh_fast(fmaxf(a0h, a1h));
        }
        uint4 pv;
        pv.x = packbf(r[0], r[1]); pv.y = packbf(r[2], r[3]);
        pv.z = packbf(r[4], r[5]); pv.w = packbf(r[6], r[7]);
        *(uint4*)&g_pooled1[(size_t)b * 1536 + (i * 32 + w) * 8] = pv;
    }
}

// ---------------- bf16 tensor-core GEMM mainloop (shared) ----------------
// BM=64, BN (96|128), BK=32 (2x k16), 3 cp.async stages. smem rows as u32
// bf16-pairs, row stride 20 u32 (16 data + 4 pad).
template <int BN>
__device__ __forceinline__ void gemm_mainloop(
    const __nv_bfloat16* __restrict__ A, const __nv_bfloat16* __restrict__ Wt,
    int K, int m0, u32* smem, int tid, float (&acc)[2][BN / 32][4]) {
    constexpr int TN = BN / 32;
    constexpr int RST = 20;
    constexpr int ASZ = 64 * RST;
    constexpr int WSZ = BN * RST;
    constexpr int WCP = BN * 4;
    constexpr int STG = ASZ + WSZ;

    const int lane = tid & 31, warp = tid >> 5;
    const int wm_base = (warp >> 2) * 32;
    const int wn_base = (warp & 3) * (BN / 4);
    const int gid = lane >> 2, tig = lane & 3;
    const int arow = tid >> 2, a4 = tid & 3;

    auto load_stage = [&](int buf, int k0) {
        u32* sA = smem + buf * STG;
        u32* sW = sA + ASZ;
        bool pa = (k0 + a4 * 8) < K;
        cp16(&sA[arow * RST + a4 * 4],
             pa ? (const void*)(A + (size_t)(m0 + arow) * K + k0 + a4 * 8) : (const void*)A, pa);
        #pragma unroll
        for (int i = 0; i < (WCP + 255) / 256; i++) {
            int idx = tid + i * 256;
            if (WCP % 256 == 0 || idx < WCP) {
                int wr = idx >> 2, w4 = idx & 3;
                bool p = (k0 + w4 * 8) < K;
                cp16(&sW[wr * RST + w4 * 4],
                     p ? (const void*)(Wt + (size_t)wr * K + k0 + w4 * 8) : (const void*)Wt, p);
            }
        }
    };

    const int nk = (K + 31) >> 5;
    load_stage(0, 0);
    cp_commit();
    if (nk > 1) { load_stage(1, 32); cp_commit(); }

    int buf = 0;
    for (int kt = 0; kt < nk; kt++) {
        if (kt + 2 < nk) {
            load_stage((buf + 2) % 3, (kt + 2) * 32);
            cp_commit();
            cp_wait<2>();
        } else if (kt + 1 < nk) {
            cp_wait<1>();
        } else {
            cp_wait<0>();
        }
        __syncthreads();

        const int k0 = kt << 5;
        const u32* pA = smem + buf * STG;
        const u32* pW = pA + ASZ;
        #pragma unroll
        for (int ks = 0; ks < 2; ks++) {
            if (k0 + ks * 16 < K) {
                const int kb = ks * 8;
                u32 af[2][4];
                #pragma unroll
                for (int wm = 0; wm < 2; wm++) {
                    int r = wm_base + wm * 16;
                    af[wm][0] = pA[(r + gid)     * RST + kb + tig];
                    af[wm][1] = pA[(r + gid + 8) * RST + kb + tig];
                    af[wm][2] = pA[(r + gid)     * RST + kb + tig + 4];
                    af[wm][3] = pA[(r + gid + 8) * RST + kb + tig + 4];
                }
                u32 bf[TN][2];
                #pragma unroll
                for (int jn = 0; jn < TN; jn++) {
                    int c = wn_base + jn * 8 + gid;
                    bf[jn][0] = pW[c * RST + kb + tig];
                    bf[jn][1] = pW[c * RST + kb + tig + 4];
                }
                #pragma unroll
                for (int wm = 0; wm < 2; wm++)
                    #pragma unroll
                    for (int jn = 0; jn < TN; jn++)
                        mma_bf16(acc[wm][jn], af[wm], bf[jn]);
            }
        }
        __syncthreads();
        buf = (buf + 1) % 3;
    }
}

// ---------------- fc0 + fc1 fused: one 256-CTA launch ----------------
__global__ __launch_bounds__(256) void fc01_gemm(
    const __nv_bfloat16* __restrict__ A0, const __nv_bfloat16* __restrict__ Wt0,
    const float* __restrict__ bias0,
    const __nv_bfloat16* __restrict__ A1, const __nv_bfloat16* __restrict__ Wt1,
    const float* __restrict__ bias1) {
    extern __shared__ u32 smem[];
    const int tid = threadIdx.x;
    const bool second = blockIdx.x >= (BB / 64);
    const __nv_bfloat16* A  = second ? A1 : A0;
    const __nv_bfloat16* Wt = second ? Wt1 : Wt0;
    const float* bias       = second ? bias1 : bias0;
    const int K    = second ? 1536 : 3328;
    const int ooff = second ? (528 + 30 * 32) : (528 + 27 * 32);
    const int m0 = (blockIdx.x & (BB / 64 - 1)) * 64;

    float acc[2][3][4];
    #pragma unroll
    for (int i = 0; i < 2; i++)
        #pragma unroll
        for (int j = 0; j < 3; j++)
            #pragma unroll
            for (int q = 0; q < 4; q++) acc[i][j][q] = 0.f;

    gemm_mainloop<96>(A, Wt, K, m0, smem, tid, acc);

    const int lane = tid & 31, warp = tid >> 5;
    const int wm_base = (warp >> 2) * 32;
    const int wn_base = (warp & 3) * 24;
    const int gid = lane >> 2, tig = lane & 3;
    __nv_bfloat16* C = g_h;
    #pragma unroll
    for (int wm = 0; wm < 2; wm++) {
        int r0 = m0 + wm_base + wm * 16 + gid;
        #pragma unroll
        for (int jn = 0; jn < 3; jn++) {
            int cl = wn_base + jn * 8 + tig * 2;
            float b0v = bias[cl], b1v = bias[cl + 1];
            float v0 = tanh_fast(acc[wm][jn][0] + b0v);
            float v1 = tanh_fast(acc[wm][jn][1] + b1v);
            float v2 = tanh_fast(acc[wm][jn][2] + b0v);
            float v3 = tanh_fast(acc[wm][jn][3] + b1v);
            *(u32*)&C[(size_t)r0 * 1584 + ooff + cl]       = packbf(v0, v1);
            *(u32*)&C[(size_t)(r0 + 8) * 1584 + ooff + cl] = packbf(v2, v3);
        }
    }
}

// ---------------- mlp GEMM + BN + out dot + sigmoid ----------------
__global__ __launch_bounds__(256) void mlp_gemm(
    const __nv_bfloat16* __restrict__ A, const __nv_bfloat16* __restrict__ Wt,
    const float* __restrict__ bias, float* __restrict__ C,
    const float* __restrict__ gamma, const float* __restrict__ beta,
    const float* __restrict__ mean, const float* __restrict__ var,
    const float* __restrict__ oW, const float* __restrict__ ob) {
    extern __shared__ u32 smem[];
    const int tid = threadIdx.x;
    const int lane = tid & 31, warp = tid >> 5;
    const int wm_base = (warp >> 2) * 32;
    const int wn_base = (warp & 3) * 32;
    const int gid = lane >> 2, tig = lane & 3;
    const int m0 = blockIdx.x * 64;

    float acc[2][4][4];
    #pragma unroll
    for (int i = 0; i < 2; i++)
        #pragma unroll
        for (int j = 0; j < 4; j++)
            #pragma unroll
            for (int q = 0; q < 4; q++) acc[i][j][q] = 0.f;

    gemm_mainloop<128>(A, Wt, 1584, m0, smem, tid, acc);

    constexpr int HST = 132;
    float* hb  = (float*)smem;          // [64][132]
    float* wsm = (float*)smem + 64 * HST;
    float* csm = wsm + 128;
    __syncthreads();
    #pragma unroll
    for (int wm = 0; wm < 2; wm++) {
        int rl0 = wm_base + wm * 16 + gid;
        #pragma unroll
        for (int jn = 0; jn < 4; jn++) {
            int cl = wn_base + jn * 8 + tig * 2;
            float b0v = bias[cl], b1v = bias[cl + 1];
            hb[rl0 * HST + cl]           = fmaxf(acc[wm][jn][0] + b0v, 0.f);
            hb[rl0 * HST + cl + 1]       = fmaxf(acc[wm][jn][1] + b1v, 0.f);
            hb[(rl0 + 8) * HST + cl]     = fmaxf(acc[wm][jn][2] + b0v, 0.f);
            hb[(rl0 + 8) * HST + cl + 1] = fmaxf(acc[wm][jn][3] + b1v, 0.f);
        }
    }
    if (tid < 128) {
        float sc = rsqrtf(var[tid] + 0.001f) * gamma[tid];
        wsm[tid] = sc * oW[tid];
        csm[tid] = (beta[tid] - mean[tid] * sc) * oW[tid];
    }
    __syncthreads();
    float ob0 = ob[0];
    float4 wv = *(float4*)&wsm[lane * 4];
    float4 cv = *(float4*)&csm[lane * 4];
    float cadd = cv.x + cv.y + cv.z + cv.w;
    #pragma unroll
    for (int q = 0; q < 8; q++) {
        int r = warp * 8 + q;
        float4 hv = *(float4*)&hb[r * HST + lane * 4];
        float s = hv.x * wv.x + hv.y * wv.y + hv.z * wv.z + hv.w * wv.w + cadd;
        #pragma unroll
        for (int o2 = 16; o2; o2 >>= 1) s += __shfl_xor_sync(0xffffffffu, s, o2);
        if (lane == 0) C[m0 + r] = 1.f / (1.f + expf(-(s + ob0)));
    }
}

// ---------------- gram: fp32 smem + fma2 + (i,j) LUT ----------------
__global__ __launch_bounds__(256) void gram_kernel() {
    __shared__ __align__(16) float as[33 * 38];   // [row][38]: even stride, u64-aligned
    int b = blockIdx.x, tid = threadIdx.x;
    __nv_bfloat16* hrow = &g_h[(size_t)b * 1584];
    const u32* augu = (const u32*)(hrow + 528);   // 528 u32 = 1056 bf16
    // convert once: bf16 pair -> 2 fp32
    for (int i = tid; i < 528; i += 256) {
        int n = i >> 4, d = i & 15;
        u32 v = augu[i];
        float2 f = __bfloat1622float2(*(const __nv_bfloat162*)&v);
        as[n * 38 + 2 * d]     = f.x;
        as[n * 38 + 2 * d + 1] = f.y;
    }
    __syncthreads();
    for (int p = tid; p < 528; p += 256) {
        u32 ij = g_ij[p];
        const u64* ra = (const u64*)&as[ij >> 16];
        const u64* rb = (const u64*)&as[ij & 0xffffu];
        u64 s0 = 0, s1 = 0;   // packed 0.0f pairs
        #pragma unroll
        for (int d = 0; d < 16; d += 2) {
            s0 = fma2(ra[d],     rb[d],     s0);
            s1 = fma2(ra[d + 1], rb[d + 1], s1);
        }
        float a, bq, c, dq;
        upk2(s0, a, bq);
        upk2(s1, c, dq);
        hrow[p] = __float2bfloat16_rn((a + c) + (bq + dq));
    }
}

// ---------------- launch ----------------
extern "C" void kernel_launch(void* const* d_in, const int* in_sizes, int n_in,
                              void* d_out, int out_size) {
    const int*   sparse  = (const int*)d_in[0];
    const float* dense   = (const float*)d_in[1];
    const float* gtab    = (const float*)d_in[2];
    const float* gW      = (const float*)d_in[3];
    const float* gb      = (const float*)d_in[4];
    const float* ctab    = (const float*)d_in[5];
    const float* cW      = (const float*)d_in[6];
    const float* cb      = (const float*)d_in[7];
    const float* k0      = (const float*)d_in[8];
    const float* b0      = (const float*)d_in[9];
    const float* fcW0    = (const float*)d_in[10];
    const float* fcb0    = (const float*)d_in[11];
    const float* k1      = (const float*)d_in[12];
    const float* b1      = (const float*)d_in[13];
    const float* fcW1    = (const float*)d_in[14];
    const float* fcb1    = (const float*)d_in[15];
    const float* mlpW    = (const float*)d_in[16];
    const float* mlpb    = (const float*)d_in[17];
    const float* bng     = (const float*)d_in[18];
    const float* bnb     = (const float*)d_in[19];
    const float* bnm     = (const float*)d_in[20];
    const float* bnv     = (const float*)d_in[21];
    const float* oW      = (const float*)d_in[22];
    const float* ob      = (const float*)d_in[23];
    float* out = (float*)d_out;

    void *p0, *p1, *ph, *w0, *w1, *w2;
    cudaGetSymbolAddress(&p0, g_pooled0);
    cudaGetSymbolAddress(&p1, g_pooled1);
    cudaGetSymbolAddress(&ph, g_h);
    cudaGetSymbolAddress(&w0, g_Wt0);
    cudaGetSymbolAddress(&w1, g_Wt1);
    cudaGetSymbolAddress(&w2, g_Wt2);

    const int smem96  = 3 * (64 * 20 + 96 * 20) * 4;    // 38400
    const int smem128 = 3 * (64 * 20 + 128 * 20) * 4;   // 46080 (> epilogue's 34816)
    cudaFuncSetAttribute(fc01_gemm,
                         cudaFuncAttributeMaxDynamicSharedMemorySize, smem96);
    cudaFuncSetAttribute(mlp_gemm,
                         cudaFuncAttributeMaxDynamicSharedMemorySize, smem128);

    convW_all<<<dim3(104, 10), dim3(32, 8)>>>(fcW0, fcW1, mlpW,
        (__nv_bfloat16*)w0, (__nv_bfloat16*)w1, (__nv_bfloat16*)w2);
    stageA_kernel<<<BB, 256>>>(sparse, dense, gtab, gW, gb, ctab, cW, cb, k0, b0, k1, b1);
    fc01_gemm<<<2 * (BB / 64), 256, smem96>>>((const __nv_bfloat16*)p0,
        (const __nv_bfloat16*)w0, fcb0,
        (const __nv_bfloat16*)p1, (const __nv_bfloat16*)w1, fcb1);
    gram_kernel<<<BB, 256>>>();
    mlp_gemm<<<BB / 64, 256, smem128>>>((const __nv_bfloat16*)ph,
        (const __nv_bfloat16*)w2, mlpb, out,
        bng, bnb, bnm, bnv, oW, ob);
}

// round 15
// speedup vs baseline: 1.0979x; 1.0979x over previous
#include <cuda_runtime.h>
#include <cuda_bf16.h>
#include <cstdint>
#include <math.h>

#define BB 8192
typedef unsigned long long u64;
typedef unsigned int u32;

// ---------------- device scratch (allocation-free) ----------------
__device__ __align__(16) __nv_bfloat16 g_pooled0[BB * 3328];
__device__ __align__(16) __nv_bfloat16 g_pooled1[BB * 1536];
__device__ __align__(16) __nv_bfloat16 g_h[BB * 1584];   // [ip(528) | aug(1056)] per row
__device__ __align__(16) __nv_bfloat16 g_Wt0[96 * 3328]; // fc0 W transposed [N][K] bf16
__device__ __align__(16) __nv_bfloat16 g_Wt1[96 * 1536];
__device__ __align__(16) __nv_bfloat16 g_Wt2[128 * 1584];

// ---------------- helpers ----------------
__device__ __forceinline__ float tanh_fast(float x) {
    float y;
    asm("tanh.approx.f32 %0, %1;" : "=f"(y) : "f"(x));
    return y;
}
__device__ __forceinline__ void cp16(void* dst, const void* src, bool p) {
    u32 d = (u32)__cvta_generic_to_shared(dst);
    int sz = p ? 16 : 0;
    asm volatile("cp.async.cg.shared.global [%0], [%1], 16, %2;\n"
                 :: "r"(d), "l"(src), "r"(sz));
}
__device__ __forceinline__ void cp_commit() { asm volatile("cp.async.commit_group;\n"); }
template <int N> __device__ __forceinline__ void cp_wait() {
    asm volatile("cp.async.wait_group %0;\n" :: "n"(N));
}
__device__ __forceinline__ void mma_bf16(float* c, const u32* a, const u32* b) {
    asm volatile(
        "mma.sync.aligned.m16n8k16.row.col.f32.bf16.bf16.f32 "
        "{%0,%1,%2,%3}, {%4,%5,%6,%7}, {%8,%9}, {%0,%1,%2,%3};\n"
        : "+f"(c[0]), "+f"(c[1]), "+f"(c[2]), "+f"(c[3])
        : "r"(a[0]), "r"(a[1]), "r"(a[2]), "r"(a[3]), "r"(b[0]), "r"(b[1]));
}
// packed f32x2 ops (sm_103a). fma2(a,b,c) = a*b + c
__device__ __forceinline__ u64 pk2(float lo, float hi) {
    u64 r; asm("mov.b64 %0, {%1, %2};" : "=l"(r) : "f"(lo), "f"(hi)); return r;
}
__device__ __forceinline__ void upk2(u64 v, float& lo, float& hi) {
    asm("mov.b64 {%0, %1}, %2;" : "=f"(lo), "=f"(hi) : "l"(v));
}
__device__ __forceinline__ u64 fma2(u64 a, u64 b, u64 c) {
    u64 d; asm("fma.rn.f32x2 %0, %1, %2, %3;" : "=l"(d) : "l"(a), "l"(b), "l"(c)); return d;
}
__device__ __forceinline__ u32 packbf(float lo, float hi) {
    __nv_bfloat162 h = __floats2bfloat162_rn(lo, hi);   // .x = lo (low address)
    return *(u32*)&h;
}

// ---------------- W transpose + convert (all three, one launch) ----------------
__device__ __forceinline__ void convW_tile(const float* __restrict__ W,
                                           __nv_bfloat16* __restrict__ Wt,
                                           int K, int N, int bx, int by,
                                           float (*t)[33], int tx, int ty) {
    int k0 = bx * 32, n0 = by * 32;
    #pragma unroll
    for (int r = 0; r < 32; r += 8) {
        int k = k0 + ty + r, n = n0 + tx;
        if (k < K && n < N) t[ty + r][tx] = W[(size_t)k * N + n];
    }
    __syncthreads();
    #pragma unroll
    for (int r = 0; r < 32; r += 8) {
        int n = n0 + ty + r, k = k0 + tx;
        if (k < K && n < N) Wt[(size_t)n * K + k] = __float2bfloat16_rn(t[tx][ty + r]);
    }
}

__global__ void convW_all(const float* __restrict__ W0, const float* __restrict__ W1,
                          const float* __restrict__ W2,
                          __nv_bfloat16* __restrict__ Wt0, __nv_bfloat16* __restrict__ Wt1,
                          __nv_bfloat16* __restrict__ Wt2) {
    __shared__ float t[32][33];
    int tx = threadIdx.x, ty = threadIdx.y;
    int y = blockIdx.y, x = blockIdx.x;
    if (y < 3) {
        convW_tile(W0, Wt0, 3328, 96, x, y, t, tx, ty);           // 104 x 3
    } else if (y < 6) {
        if (x < 48) convW_tile(W1, Wt1, 1536, 96, x, y - 3, t, tx, ty);
    } else {
        if (x < 50) convW_tile(W2, Wt2, 1584, 128, x, y - 6, t, tx, ty);
    }
}

// ---------------- stage A: embed + conv0 + pool + conv1 + pool (fused) ----------------
__global__ __launch_bounds__(256, 4) void stageA_kernel(
    const int* __restrict__ sparse, const float* __restrict__ dense,
    const float* __restrict__ gtab, const float* __restrict__ gW, const float* __restrict__ gb,
    const float* __restrict__ ctab, const float* __restrict__ cW, const float* __restrict__ cb,
    const float* __restrict__ k0, const float* __restrict__ b0,
    const float* __restrict__ k1, const float* __restrict__ b1) {
    __shared__ int sidx[26];
    __shared__ __align__(16) float xs0[27 * 32];     // gen embedding [h][w]
    __shared__ __align__(16) float xs1[8 * 416];     // conv0 pooled, CHW [c][13*32]
    __shared__ __align__(16) float ks0[56];
    __shared__ __align__(16) float ks1[448];
    __shared__ __align__(16) float bs0[8];
    __shared__ __align__(16) float bs1[8];

    int b = blockIdx.x, tid = threadIdx.x;
    if (tid < 26) sidx[tid] = sparse[b * 26 + tid];
    if (tid < 56) ks0[tid] = k0[tid];
    if (tid < 8)  bs0[tid] = b0[tid];
    if (tid >= 8 && tid < 16) bs1[tid - 8] = b1[tid - 8];
    for (int i = tid; i < 448; i += 256) ks1[i] = k1[i];
    __syncthreads();

    __nv_bfloat16* hrow = &g_h[(size_t)b * 1584 + 528];   // aug region (bf16)
    for (int i = tid; i < 832; i += 256) {
        int s = i >> 5, d = i & 31;
        int ix = sidx[s];
        xs0[i]  = gtab[ix * 32 + d];
        hrow[i] = __float2bfloat16_rn(ctab[ix * 32 + d]);
    }
    if (tid < 32) {
        int d = tid;
        float dng = gb[d], dnc = cb[d];
        float xd[13];
        #pragma unroll
        for (int j = 0; j < 13; j++) xd[j] = dense[b * 13 + j];
        #pragma unroll
        for (int j = 0; j < 13; j++) {
            dng += xd[j] * gW[j * 32 + d];
            dnc += xd[j] * cW[j * 32 + d];
        }
        xs0[832 + d]  = dng;
        hrow[832 + d] = __float2bfloat16_rn(dnc);
    }
    __syncthreads();

    // conv0 (7x1, 1->8) + pool2 + tanh, f32x2 packed over f-pairs
    for (int o = tid; o < 416; o += 256) {
        int w = o & 31, i = o >> 5;
        u64 acc0[4], acc1[4];
        #pragma unroll
        for (int fp = 0; fp < 4; fp++) {
            u64 bv = *(const u64*)&bs0[fp * 2];
            acc0[fp] = bv; acc1[fp] = bv;
        }
        #pragma unroll
        for (int k = 0; k < 7; k++) {
            int ha = 2 * i + k - 3, hb = ha + 1;
            float xa = ((unsigned)ha < 27u) ? xs0[ha * 32 + w] : 0.f;
            float xb = ((unsigned)hb < 27u) ? xs0[hb * 32 + w] : 0.f;
            u64 xap = pk2(xa, xa), xbp = pk2(xb, xb);
            #pragma unroll
            for (int fp = 0; fp < 4; fp++) {
                u64 kp = *(const u64*)&ks0[k * 8 + fp * 2];
                acc0[fp] = fma2(xap, kp, acc0[fp]);
                acc1[fp] = fma2(xbp, kp, acc1[fp]);
            }
        }
        float r[8];
        #pragma unroll
        for (int fp = 0; fp < 4; fp++) {
            float a0l, a0h, a1l, a1h;
            upk2(acc0[fp], a0l, a0h);
            upk2(acc1[fp], a1l, a1h);
            r[fp * 2]     = tanh_fast(fmaxf(a0l, a1l));
            r[fp * 2 + 1] = tanh_fast(fmaxf(a0h, a1h));
        }
        uint4 pv;
        pv.x = packbf(r[0], r[1]); pv.y = packbf(r[2], r[3]);
        pv.z = packbf(r[4], r[5]); pv.w = packbf(r[6], r[7]);
        *(uint4*)&g_pooled0[(size_t)b * 3328 + (i * 32 + w) * 8] = pv;
        #pragma unroll
        for (int f = 0; f < 8; f++) xs1[f * 416 + i * 32 + w] = r[f];
    }
    __syncthreads();

    // conv1 (7x1, 8->8) + pool2 + tanh; CHW smem reads, f32x2 packed.
    // k-loop rolled to cap live registers under the 64-reg budget (no spills).
    if (tid < 192) {
        int w = tid & 31, i = tid >> 5;   // i in 0..5
        u64 acc0[4], acc1[4];
        #pragma unroll
        for (int fp = 0; fp < 4; fp++) {
            u64 bv = *(const u64*)&bs1[fp * 2];
            acc0[fp] = bv; acc1[fp] = bv;
        }
        #pragma unroll 1
        for (int k = 0; k < 7; k++) {
            int ha = 2 * i + k - 3, hb = ha + 1;
            bool pa = (unsigned)ha < 13u, pb = (unsigned)hb < 13u;
            #pragma unroll
            for (int c = 0; c < 8; c++) {
                float xa = pa ? xs1[c * 416 + ha * 32 + w] : 0.f;
                float xb = pb ? xs1[c * 416 + hb * 32 + w] : 0.f;
                u64 xap = pk2(xa, xa), xbp = pk2(xb, xb);
                #pragma unroll
                for (int fp = 0; fp < 4; fp++) {
                    u64 kp = *(const u64*)&ks1[(k * 8 + c) * 8 + fp * 2];
                    acc0[fp] = fma2(xap, kp, acc0[fp]);
                    acc1[fp] = fma2(xbp, kp, acc1[fp]);
                }
            }
        }
        float r[8];
        #pragma unroll
        for (int fp = 0; fp < 4; fp++) {
            float a0l, a0h, a1l, a1h;
            upk2(acc0[fp], a0l, a0h);
            upk2(acc1[fp], a1l, a1h);
            r[fp * 2]     = tanh_fast(fmaxf(a0l, a1l));
            r[fp * 2 + 1] = tanh_fast(fmaxf(a0h, a1h));
        }
        uint4 pv;
        pv.x = packbf(r[0], r[1]); pv.y = packbf(r[2], r[3]);
        pv.z = packbf(r[4], r[5]); pv.w = packbf(r[6], r[7]);
        *(uint4*)&g_pooled1[(size_t)b * 1536 + (i * 32 + w) * 8] = pv;
    }
}

// ---------------- bf16 tensor-core GEMM mainloop (shared) ----------------
// BM=64, BN (96|128), BK=32 (2x k16), 3 cp.async stages. smem rows as u32
// bf16-pairs, row stride 20 u32 (16 data + 4 pad).
template <int BN>
__device__ __forceinline__ void gemm_mainloop(
    const __nv_bfloat16* __restrict__ A, const __nv_bfloat16* __restrict__ Wt,
    int K, int m0, u32* smem, int tid, float (&acc)[2][BN / 32][4]) {
    constexpr int TN = BN / 32;
    constexpr int RST = 20;
    constexpr int ASZ = 64 * RST;
    constexpr int WSZ = BN * RST;
    constexpr int WCP = BN * 4;
    constexpr int STG = ASZ + WSZ;

    const int lane = tid & 31, warp = tid >> 5;
    const int wm_base = (warp >> 2) * 32;
    const int wn_base = (warp & 3) * (BN / 4);
    const int gid = lane >> 2, tig = lane & 3;
    const int arow = tid >> 2, a4 = tid & 3;

    auto load_stage = [&](int buf, int k0) {
        u32* sA = smem + buf * STG;
        u32* sW = sA + ASZ;
        bool pa = (k0 + a4 * 8) < K;
        cp16(&sA[arow * RST + a4 * 4],
             pa ? (const void*)(A + (size_t)(m0 + arow) * K + k0 + a4 * 8) : (const void*)A, pa);
        #pragma unroll
        for (int i = 0; i < (WCP + 255) / 256; i++) {
            int idx = tid + i * 256;
            if (WCP % 256 == 0 || idx < WCP) {
                int wr = idx >> 2, w4 = idx & 3;
                bool p = (k0 + w4 * 8) < K;
                cp16(&sW[wr * RST + w4 * 4],
                     p ? (const void*)(Wt + (size_t)wr * K + k0 + w4 * 8) : (const void*)Wt, p);
            }
        }
    };

    const int nk = (K + 31) >> 5;
    load_stage(0, 0);
    cp_commit();
    if (nk > 1) { load_stage(1, 32); cp_commit(); }

    int buf = 0;
    for (int kt = 0; kt < nk; kt++) {
        if (kt + 2 < nk) {
            load_stage((buf + 2) % 3, (kt + 2) * 32);
            cp_commit();
            cp_wait<2>();
        } else if (kt + 1 < nk) {
            cp_wait<1>();
        } else {
            cp_wait<0>();
        }
        __syncthreads();

        const int k0 = kt << 5;
        const u32* pA = smem + buf * STG;
        const u32* pW = pA + ASZ;
        #pragma unroll
        for (int ks = 0; ks < 2; ks++) {
            if (k0 + ks * 16 < K) {
                const int kb = ks * 8;
                u32 af[2][4];
                #pragma unroll
                for (int wm = 0; wm < 2; wm++) {
                    int r = wm_base + wm * 16;
                    af[wm][0] = pA[(r + gid)     * RST + kb + tig];
                    af[wm][1] = pA[(r + gid + 8) * RST + kb + tig];
                    af[wm][2] = pA[(r + gid)     * RST + kb + tig + 4];
                    af[wm][3] = pA[(r + gid + 8) * RST + kb + tig + 4];
                }
                u32 bf[TN][2];
                #pragma unroll
                for (int jn = 0; jn < TN; jn++) {
                    int c = wn_base + jn * 8 + gid;
                    bf[jn][0] = pW[c * RST + kb + tig];
                    bf[jn][1] = pW[c * RST + kb + tig + 4];
                }
                #pragma unroll
                for (int wm = 0; wm < 2; wm++)
                    #pragma unroll
                    for (int jn = 0; jn < TN; jn++)
                        mma_bf16(acc[wm][jn], af[wm], bf[jn]);
            }
        }
        __syncthreads();
        buf = (buf + 1) % 3;
    }
}

// ---------------- fc0 + fc1 fused: one 256-CTA launch ----------------
__global__ __launch_bounds__(256) void fc01_gemm(
    const __nv_bfloat16* __restrict__ A0, const __nv_bfloat16* __restrict__ Wt0,
    const float* __restrict__ bias0,
    const __nv_bfloat16* __restrict__ A1, const __nv_bfloat16* __restrict__ Wt1,
    const float* __restrict__ bias1) {
    extern __shared__ u32 smem[];
    const int tid = threadIdx.x;
    const bool second = blockIdx.x >= (BB / 64);
    const __nv_bfloat16* A  = second ? A1 : A0;
    const __nv_bfloat16* Wt = second ? Wt1 : Wt0;
    const float* bias       = second ? bias1 : bias0;
    const int K    = second ? 1536 : 3328;
    const int ooff = second ? (528 + 30 * 32) : (528 + 27 * 32);
    const int m0 = (blockIdx.x & (BB / 64 - 1)) * 64;

    float acc[2][3][4];
    #pragma unroll
    for (int i = 0; i < 2; i++)
        #pragma unroll
        for (int j = 0; j < 3; j++)
            #pragma unroll
            for (int q = 0; q < 4; q++) acc[i][j][q] = 0.f;

    gemm_mainloop<96>(A, Wt, K, m0, smem, tid, acc);

    const int lane = tid & 31, warp = tid >> 5;
    const int wm_base = (warp >> 2) * 32;
    const int wn_base = (warp & 3) * 24;
    const int gid = lane >> 2, tig = lane & 3;
    __nv_bfloat16* C = g_h;
    #pragma unroll
    for (int wm = 0; wm < 2; wm++) {
        int r0 = m0 + wm_base + wm * 16 + gid;
        #pragma unroll
        for (int jn = 0; jn < 3; jn++) {
            int cl = wn_base + jn * 8 + tig * 2;
            float b0v = bias[cl], b1v = bias[cl + 1];
            float v0 = tanh_fast(acc[wm][jn][0] + b0v);
            float v1 = tanh_fast(acc[wm][jn][1] + b1v);
            float v2 = tanh_fast(acc[wm][jn][2] + b0v);
            float v3 = tanh_fast(acc[wm][jn][3] + b1v);
            *(u32*)&C[(size_t)r0 * 1584 + ooff + cl]       = packbf(v0, v1);
            *(u32*)&C[(size_t)(r0 + 8) * 1584 + ooff + cl] = packbf(v2, v3);
        }
    }
}

// ---------------- mlp GEMM + BN + out dot + sigmoid ----------------
__global__ __launch_bounds__(256) void mlp_gemm(
    const __nv_bfloat16* __restrict__ A, const __nv_bfloat16* __restrict__ Wt,
    const float* __restrict__ bias, float* __restrict__ C,
    const float* __restrict__ gamma, const float* __restrict__ beta,
    const float* __restrict__ mean, const float* __restrict__ var,
    const float* __restrict__ oW, const float* __restrict__ ob) {
    extern __shared__ u32 smem[];
    const int tid = threadIdx.x;
    const int lane = tid & 31, warp = tid >> 5;
    const int wm_base = (warp >> 2) * 32;
    const int wn_base = (warp & 3) * 32;
    const int gid = lane >> 2, tig = lane & 3;
    const int m0 = blockIdx.x * 64;

    float acc[2][4][4];
    #pragma unroll
    for (int i = 0; i < 2; i++)
        #pragma unroll
        for (int j = 0; j < 4; j++)
            #pragma unroll
            for (int q = 0; q < 4; q++) acc[i][j][q] = 0.f;

    gemm_mainloop<128>(A, Wt, 1584, m0, smem, tid, acc);

    constexpr int HST = 132;
    float* hb  = (float*)smem;          // [64][132]
    float* wsm = (float*)smem + 64 * HST;
    float* csm = wsm + 128;
    __syncthreads();
    #pragma unroll
    for (int wm = 0; wm < 2; wm++) {
        int rl0 = wm_base + wm * 16 + gid;
        #pragma unroll
        for (int jn = 0; jn < 4; jn++) {
            int cl = wn_base + jn * 8 + tig * 2;
            float b0v = bias[cl], b1v = bias[cl + 1];
            hb[rl0 * HST + cl]           = fmaxf(acc[wm][jn][0] + b0v, 0.f);
            hb[rl0 * HST + cl + 1]       = fmaxf(acc[wm][jn][1] + b1v, 0.f);
            hb[(rl0 + 8) * HST + cl]     = fmaxf(acc[wm][jn][2] + b0v, 0.f);
            hb[(rl0 + 8) * HST + cl + 1] = fmaxf(acc[wm][jn][3] + b1v, 0.f);
        }
    }
    if (tid < 128) {
        float sc = rsqrtf(var[tid] + 0.001f) * gamma[tid];
        wsm[tid] = sc * oW[tid];
        csm[tid] = (beta[tid] - mean[tid] * sc) * oW[tid];
    }
    __syncthreads();
    float ob0 = ob[0];
    float4 wv = *(float4*)&wsm[lane * 4];
    float4 cv = *(float4*)&csm[lane * 4];
    float cadd = cv.x + cv.y + cv.z + cv.w;
    #pragma unroll
    for (int q = 0; q < 8; q++) {
        int r = warp * 8 + q;
        float4 hv = *(float4*)&hb[r * HST + lane * 4];
        float s = hv.x * wv.x + hv.y * wv.y + hv.z * wv.z + hv.w * wv.w + cadd;
        #pragma unroll
        for (int o2 = 16; o2; o2 >>= 1) s += __shfl_xor_sync(0xffffffffu, s, o2);
        if (lane == 0) C[m0 + r] = 1.f / (1.f + expf(-(s + ob0)));
    }
}

// ---------------- gram via tensor cores: per-sample 33x33x32 A·A^T ----------------
// 8 warps = 8 m16n8 tiles covering the upper triangle:
//   warps 0-4: mt=0 (rows 0-15),  nt=0..4
//   warps 5-7: mt=1 (rows 16-31), nt=2..4
// Row 32 appears only as a column (nt=4). B-columns 33-39 read garbage smem and
// are discarded in the epilogue (C[i][j] depends only on row i / col j).
__global__ __launch_bounds__(256) void gram_kernel() {
    __shared__ __align__(16) u32 sm[40 * 20];   // rows stride 20 u32 (conflict-free)
    int b = blockIdx.x, tid = threadIdx.x;
    __nv_bfloat16* hrow = &g_h[(size_t)b * 1584];
    const u32* augu = (const u32*)(hrow + 528);  // 528 u32 = 33 rows x 16 u32
    for (int i = tid; i < 528; i += 256)
        sm[(i >> 4) * 20 + (i & 15)] = augu[i];
    __syncthreads();

    const int warp = tid >> 5, lane = tid & 31;
    const int gid = lane >> 2, tig = lane & 3;
    const int mt = (warp >= 5) ? 1 : 0;
    const int nt = (warp >= 5) ? (warp - 3) : warp;

    float c[4] = {0.f, 0.f, 0.f, 0.f};
    const int r0 = mt * 16 + gid;
    const int cc = nt * 8 + gid;
    #pragma unroll
    for (int kc = 0; kc < 2; kc++) {
        const int kb = kc * 8;
        u32 a[4], bf[2];
        a[0] = sm[r0 * 20 + kb + tig];
        a[1] = sm[(r0 + 8) * 20 + kb + tig];
        a[2] = sm[r0 * 20 + kb + tig + 4];
        a[3] = sm[(r0 + 8) * 20 + kb + tig + 4];
        bf[0] = sm[cc * 20 + kb + tig];
        bf[1] = sm[cc * 20 + kb + tig + 4];
        mma_bf16(c, a, bf);
    }

    const int i0 = mt * 16 + gid;
    const int j0 = nt * 8 + tig * 2;
    #pragma unroll
    for (int e = 0; e < 4; e++) {
        int i = i0 + (e >> 1) * 8;
        int j = j0 + (e & 1);
        if (j > i && j < 33) {
            int p = i * (65 - i) / 2 + (j - i - 1);
            hrow[p] = __float2bfloat16_rn(c[e]);
        }
    }
}

// ---------------- launch ----------------
extern "C" void kernel_launch(void* const* d_in, const int* in_sizes, int n_in,
                              void* d_out, int out_size) {
    const int*   sparse  = (const int*)d_in[0];
    const float* dense   = (const float*)d_in[1];
    const float* gtab    = (const float*)d_in[2];
    const float* gW      = (const float*)d_in[3];
    const float* gb      = (const float*)d_in[4];
    const float* ctab    = (const float*)d_in[5];
    const float* cW      = (const float*)d_in[6];
    const float* cb      = (const float*)d_in[7];
    const float* k0      = (const float*)d_in[8];
    const float* b0      = (const float*)d_in[9];
    const float* fcW0    = (const float*)d_in[10];
    const float* fcb0    = (const float*)d_in[11];
    const float* k1      = (const float*)d_in[12];
    const float* b1      = (const float*)d_in[13];
    const float* fcW1    = (const float*)d_in[14];
    const float* fcb1    = (const float*)d_in[15];
    const float* mlpW    = (const float*)d_in[16];
    const float* mlpb    = (const float*)d_in[17];
    const float* bng     = (const float*)d_in[18];
    const float* bnb     = (const float*)d_in[19];
    const float* bnm     = (const float*)d_in[20];
    const float* bnv     = (const float*)d_in[21];
    const float* oW      = (const float*)d_in[22];
    const float* ob      = (const float*)d_in[23];
    float* out = (float*)d_out;

    void *p0, *p1, *ph, *w0, *w1, *w2;
    cudaGetSymbolAddress(&p0, g_pooled0);
    cudaGetSymbolAddress(&p1, g_pooled1);
    cudaGetSymbolAddress(&ph, g_h);
    cudaGetSymbolAddress(&w0, g_Wt0);
    cudaGetSymbolAddress(&w1, g_Wt1);
    cudaGetSymbolAddress(&w2, g_Wt2);

    const int smem96  = 3 * (64 * 20 + 96 * 20) * 4;    // 38400
    const int smem128 = 3 * (64 * 20 + 128 * 20) * 4;   // 46080 (> epilogue's 34816)
    cudaFuncSetAttribute(fc01_gemm,
                         cudaFuncAttributeMaxDynamicSharedMemorySize, smem96);
    cudaFuncSetAttribute(mlp_gemm,
                         cudaFuncAttributeMaxDynamicSharedMemorySize, smem128);

    convW_all<<<dim3(104, 10), dim3(32, 8)>>>(fcW0, fcW1, mlpW,
        (__nv_bfloat16*)w0, (__nv_bfloat16*)w1, (__nv_bfloat16*)w2);
    stageA_kernel<<<BB, 256>>>(sparse, dense, gtab, gW, gb, ctab, cW, cb, k0, b0, k1, b1);
    fc01_gemm<<<2 * (BB / 64), 256, smem96>>>((const __nv_bfloat16*)p0,
        (const __nv_bfloat16*)w0, fcb0,
        (const __nv_bfloat16*)p1, (const __nv_bfloat16*)w1, fcb1);
    gram_kernel<<<BB, 256>>>();
    mlp_gemm<<<BB / 64, 256, smem128>>>((const __nv_bfloat16*)ph,
        (const __nv_bfloat16*)w2, mlpb, out,
        bng, bnb, bnm, bnv, oW, ob);
}